// round 15
// baseline (speedup 1.0000x reference)
#include <cuda_runtime.h>
#include <cuda_fp16.h>
#include <cstdint>
#include <cstddef>

// Problem constants
#define N_NODES  100000
#define N_EDGES  400000
#define N_GRAPHS 4000
#define IN_DIM   128
#define HID      512
#define N_DESC   200
#define XDIM     (HID + N_DESC)   // 712
#define XPAD     768              // multiple of 64 (BK)
#define MLP1     500
#define MLP1PAD  512
#define MLP2     100
#define NSCAN_BLOCKS ((N_NODES + 255) / 256)   // 391

// ===========================================================================
// PTX helpers (plain sm_80-era features only)
// ===========================================================================
__device__ __forceinline__ uint32_t smem_to_u32(const void* p) {
    uint32_t a;
    asm("{ .reg .u64 t; cvta.to.shared.u64 t, %1; cvt.u32.u64 %0, t; }"
        : "=r"(a) : "l"(p));
    return a;
}
__device__ __forceinline__ void ldsm_x4(uint32_t& r0, uint32_t& r1,
                                        uint32_t& r2, uint32_t& r3,
                                        uint32_t addr) {
    asm volatile("ldmatrix.sync.aligned.m8n8.x4.shared.b16 {%0,%1,%2,%3}, [%4];"
                 : "=r"(r0), "=r"(r1), "=r"(r2), "=r"(r3) : "r"(addr));
}
__device__ __forceinline__ void mma_fp16(float* c, const uint32_t* a,
                                         uint32_t b0, uint32_t b1) {
    asm volatile(
        "mma.sync.aligned.m16n8k16.row.col.f32.f16.f16.f32 "
        "{%0,%1,%2,%3}, {%4,%5,%6,%7}, {%8,%9}, {%0,%1,%2,%3};"
        : "+f"(c[0]), "+f"(c[1]), "+f"(c[2]), "+f"(c[3])
        : "r"(a[0]), "r"(a[1]), "r"(a[2]), "r"(a[3]), "r"(b0), "r"(b1));
}
__device__ __forceinline__ void cpa16(uint32_t s, const void* g, uint32_t sz) {
    asm volatile("cp.async.cg.shared.global [%0], [%1], 16, %2;"
                 :: "r"(s), "l"(g), "r"(sz));
}
#define CP_COMMIT() asm volatile("cp.async.commit_group;" ::: "memory")
#define CP_WAIT(n)  asm volatile("cp.async.wait_group %0;" :: "n"(n) : "memory")

// ===========================================================================
// Device scratch
// ===========================================================================
__device__ __align__(16) int g_deg[N_NODES];
__device__ __align__(16) int g_off[N_NODES + 4];
__device__ __align__(16) int g_cur[N_NODES];
__device__ int g_csr[N_EDGES];
// Decoupled-lookback state: high 32 bits = flag (0 invalid, 1 aggregate,
// 2 inclusive-prefix), low 32 bits = value. Zeroed per call by init_kernel.
__device__ unsigned long long g_state[NSCAN_BLOCKS];

__device__ __half g_a0 [(size_t)N_NODES * IN_DIM];
__device__ __half g_h1 [(size_t)N_NODES * HID];
__device__ __half g_a1 [(size_t)N_NODES * HID];
__device__ __half g_h2 [(size_t)N_NODES * HID];
__device__ __half g_X  [(size_t)N_GRAPHS * XPAD];
__device__ float  g_m1 [(size_t)N_GRAPHS * MLP1];

// Weight images: B^T fp16, [Npad][Kpad], k-contiguous
__device__ __half g_B1[512 * 128];
__device__ __half g_B2[512 * 512];
__device__ __half g_BL[MLP1PAD * XPAD];

// ===========================================================================
// Fused init: zero g_deg + zero scan state + prep all three weight images
// ===========================================================================
#define Z0 (N_NODES)
#define ZF (NSCAN_BLOCKS)
#define Z1 (512 * 128)
#define Z2 (512 * 512)
#define Z3 (MLP1PAD * XPAD)
#define INIT_TOTAL (Z0 + ZF + Z1 + Z2 + Z3)

__device__ __forceinline__ void prep_one(const float* __restrict__ W,
                                         __half* __restrict__ B,
                                         int local, int K_real, int N_real,
                                         int Kpad) {
    int n = local / Kpad, k = local % Kpad;
    float v = (k < K_real && n < N_real) ? W[(size_t)k * N_real + n] : 0.f;
    B[local] = __float2half_rn(v);
}

__global__ void init_kernel(const float* __restrict__ W1,
                            const float* __restrict__ W2,
                            const float* __restrict__ lw1,
                            __half* __restrict__ B1, __half* __restrict__ B2,
                            __half* __restrict__ BL) {
    int idx = blockIdx.x * blockDim.x + threadIdx.x;
    if (idx < Z0) {
        g_deg[idx] = 0;
    } else if (idx < Z0 + ZF) {
        g_state[idx - Z0] = 0ULL;
    } else if (idx < Z0 + ZF + Z1) {
        prep_one(W1, B1, idx - Z0 - ZF, IN_DIM, HID, 128);
    } else if (idx < Z0 + ZF + Z1 + Z2) {
        prep_one(W2, B2, idx - Z0 - ZF - Z1, HID, HID, 512);
    } else if (idx < INIT_TOTAL) {
        prep_one(lw1, BL, idx - Z0 - ZF - Z1 - Z2, XDIM, MLP1, XPAD);
    }
}

// ===========================================================================
// CSR construction: count -> single-pass lookback scan -> fill
// ===========================================================================
__global__ void count_deg_kernel(const int* __restrict__ dst) {
    int e = blockIdx.x * blockDim.x + threadIdx.x;
    if (e < N_EDGES) atomicAdd(&g_deg[dst[e]], 1);
}

// Single-pass exclusive scan with decoupled lookback. All 391 blocks are
// simultaneously resident (148 SMs x >=4 CTAs), so spinning is deadlock-free.
// flag/value packed in one 64-bit word -> single-atomic publish/read.
__global__ __launch_bounds__(256)
void scan_lookback_kernel() {
    __shared__ int part[256];
    __shared__ int s_excl;
    const int t = threadIdx.x;
    const int b = blockIdx.x;
    int i = b * 256 + t;
    int d = (i < N_NODES) ? g_deg[i] : 0;
    part[t] = d;
    __syncthreads();
    for (int off = 1; off < 256; off <<= 1) {
        int v = (t >= off) ? part[t - off] : 0;
        __syncthreads();
        part[t] += v;
        __syncthreads();
    }
    const int total = part[255];

    if (t == 0) {
        if (b == 0) {
            atomicExch(&g_state[0], (2ULL << 32) | (unsigned int)total);
            s_excl = 0;
        } else {
            atomicExch(&g_state[b], (1ULL << 32) | (unsigned int)total);
            int excl = 0;
            int idx = b - 1;
            while (true) {
                unsigned long long s;
                do {
                    s = atomicAdd(&g_state[idx], 0ULL);
                } while ((s >> 32) == 0ULL);
                excl += (int)(s & 0xFFFFFFFFULL);
                if ((s >> 32) == 2ULL) break;
                idx--;
            }
            atomicExch(&g_state[b], (2ULL << 32) | (unsigned int)(excl + total));
            s_excl = excl;
        }
    }
    __syncthreads();
    const int base = s_excl;
    if (i < N_NODES) {
        int off = base + part[t] - d;   // exclusive prefix
        g_off[i] = off;
        g_cur[i] = off;
    }
    if (b == NSCAN_BLOCKS - 1 && t == 255)
        g_off[N_NODES] = base + total;
}

__global__ void fill_csr_kernel(const int* __restrict__ src,
                                const int* __restrict__ dst) {
    int e = blockIdx.x * blockDim.x + threadIdx.x;
    if (e < N_EDGES) {
        int p = atomicAdd(&g_cur[dst[e]], 1);
        g_csr[p] = src[e];
    }
}

// ===========================================================================
// Gather-sum kernels: R7 thread structure + 2-deep software pipeline
// ===========================================================================
// fp32 features, 32 threads/node (float4), 8 nodes/block.
__global__ __launch_bounds__(256)
void gather_sum_128(const float* __restrict__ feat, __half* __restrict__ o) {
    int n = blockIdx.x * 8 + (threadIdx.x >> 5);
    int t = threadIdx.x & 31;
    int lo = g_off[n], hi = g_off[n + 1];
    float4 acc = make_float4(0.f, 0.f, 0.f, 0.f);
    int j = lo;
    if (j < hi) {
        float4 cur = reinterpret_cast<const float4*>(
            feat + (size_t)g_csr[j] * IN_DIM)[t];
        for (++j; j < hi; ++j) {
            float4 nxt = reinterpret_cast<const float4*>(
                feat + (size_t)g_csr[j] * IN_DIM)[t];
            acc.x += cur.x; acc.y += cur.y; acc.z += cur.z; acc.w += cur.w;
            cur = nxt;
        }
        acc.x += cur.x; acc.y += cur.y; acc.z += cur.z; acc.w += cur.w;
    }
    __half2 h0 = __floats2half2_rn(acc.x, acc.y);
    __half2 h1v = __floats2half2_rn(acc.z, acc.w);
    __half2* op = reinterpret_cast<__half2*>(o + (size_t)n * IN_DIM) + t * 2;
    op[0] = h0;
    op[1] = h1v;
}

// h fp16, 64 threads/node (uint4), 4 nodes/block.
__global__ __launch_bounds__(256)
void gather_sum_512h(const __half* __restrict__ h, __half* __restrict__ o) {
    int n = blockIdx.x * 4 + (threadIdx.x >> 6);
    int t = threadIdx.x & 63;
    int lo = g_off[n], hi = g_off[n + 1];
    float acc[8];
    #pragma unroll
    for (int i = 0; i < 8; i++) acc[i] = 0.f;
    int j = lo;
    if (j < hi) {
        uint4 cur = reinterpret_cast<const uint4*>(
            h + (size_t)g_csr[j] * HID)[t];
        for (++j; j < hi; ++j) {
            uint4 nxt = reinterpret_cast<const uint4*>(
                h + (size_t)g_csr[j] * HID)[t];
            const __half2* hp = reinterpret_cast<const __half2*>(&cur);
            #pragma unroll
            for (int i = 0; i < 4; i++) {
                float2 v = __half22float2(hp[i]);
                acc[i * 2 + 0] += v.x;
                acc[i * 2 + 1] += v.y;
            }
            cur = nxt;
        }
        const __half2* hp = reinterpret_cast<const __half2*>(&cur);
        #pragma unroll
        for (int i = 0; i < 4; i++) {
            float2 v = __half22float2(hp[i]);
            acc[i * 2 + 0] += v.x;
            acc[i * 2 + 1] += v.y;
        }
    }
    uint4 out;
    __half2* op = reinterpret_cast<__half2*>(&out);
    #pragma unroll
    for (int i = 0; i < 4; i++)
        op[i] = __floats2half2_rn(acc[i * 2], acc[i * 2 + 1]);
    reinterpret_cast<uint4*>(o + (size_t)n * HID)[t] = out;
}

// ===========================================================================
// fp16 tensor-core GEMM (R7-exact): C[M,Nreal] = relu(A@W + bias)
// CTA 128m x 256n, BK=64, 8 warps (32m x 128n), 2-stage cp.async.
// 144B smem rows -> conflict-free ldmatrix; smem-staged coalesced epilogue.
// ===========================================================================
#define GROW  144u
#define ATILE 18432u
#define GBUF  55296u
#define GDSM  (2 * GBUF)
#define STG_STRIDE 528u

template <bool HALF_OUT>
__global__ __launch_bounds__(256, 1)
void gemm_fp16(const __half* __restrict__ A, const __half* __restrict__ B,
               const float* __restrict__ bias, void* __restrict__ Cout,
               int M, int Nreal, int K)
{
    extern __shared__ char dsm[];
    const uint32_t sbase = smem_to_u32(dsm);
    const int tid  = threadIdx.x;
    const int lane = tid & 31;
    const int wid  = tid >> 5;
    const int row0 = blockIdx.y * 128;
    const int col0 = blockIdx.x * 256;
    const int NC   = K / 64;

    const int m_base = (wid & 3) * 32;
    const int n_base = (wid >> 2) * 128;

    float acc[2][16][4];
    #pragma unroll
    for (int i = 0; i < 2; i++)
        #pragma unroll
        for (int j = 0; j < 16; j++)
            #pragma unroll
            for (int q = 0; q < 4; q++) acc[i][j][q] = 0.f;

    auto load_chunk = [&](int buf, int c) {
        uint32_t s = sbase + (uint32_t)buf * GBUF;
        #pragma unroll
        for (int i = 0; i < 4; i++) {
            int f  = tid + i * 256;
            int m  = f >> 3, k8 = f & 7;
            int gm = row0 + m;
            uint32_t ok = (gm < M) ? 16u : 0u;
            int gmc = (gm < M) ? gm : 0;
            cpa16(s + m * GROW + k8 * 16,
                  A + (size_t)gmc * K + c * 64 + k8 * 8, ok);
        }
        #pragma unroll
        for (int i = 0; i < 8; i++) {
            int f = tid + i * 256;
            int n = f >> 3, k8 = f & 7;
            cpa16(s + ATILE + n * GROW + k8 * 16,
                  B + (size_t)(col0 + n) * K + c * 64 + k8 * 8, 16u);
        }
        CP_COMMIT();
    };

    load_chunk(0, 0);

    for (int c = 0; c < NC; c++) {
        const int buf = c & 1;
        if (c + 1 < NC) {
            load_chunk(buf ^ 1, c + 1);
            CP_WAIT(1);
        } else {
            CP_WAIT(0);
        }
        __syncthreads();

        const uint32_t sA = sbase + (uint32_t)buf * GBUF;
        const uint32_t sB = sA + ATILE;

        #pragma unroll
        for (int ks = 0; ks < 4; ks++) {
            uint32_t a[2][4];
            #pragma unroll
            for (int im = 0; im < 2; im++) {
                uint32_t ra = sA
                    + (uint32_t)(m_base + im * 16 + (lane & 15)) * GROW
                    + (uint32_t)(ks * 16 + ((lane >> 4) * 8)) * 2;
                ldsm_x4(a[im][0], a[im][1], a[im][2], a[im][3], ra);
            }
            #pragma unroll
            for (int g = 0; g < 8; g++) {
                uint32_t bh[4];
                uint32_t rb = sB
                    + (uint32_t)(n_base + g * 16 +
                                 ((lane >> 4) & 1) * 8 + (lane & 7)) * GROW
                    + (uint32_t)(ks * 16 + ((lane >> 3) & 1) * 8) * 2;
                ldsm_x4(bh[0], bh[1], bh[2], bh[3], rb);
                #pragma unroll
                for (int im = 0; im < 2; im++) {
                    #pragma unroll
                    for (int sub = 0; sub < 2; sub++) {
                        mma_fp16(acc[im][g * 2 + sub], a[im],
                                 bh[sub * 2], bh[sub * 2 + 1]);
                    }
                }
            }
        }
        __syncthreads();
    }

    const bool full_n = (col0 + 256 <= Nreal);
    if (HALF_OUT && full_n) {
        #pragma unroll
        for (int im = 0; im < 2; im++) {
            int ml = m_base + im * 16 + (lane >> 2);
            #pragma unroll
            for (int j = 0; j < 16; j++) {
                int nl = n_base + j * 8 + (lane & 3) * 2;
                float b0 = bias[col0 + nl], b1 = bias[col0 + nl + 1];
                __half2* p0 = reinterpret_cast<__half2*>(
                    dsm + (uint32_t)ml * STG_STRIDE + nl * 2);
                *p0 = __floats2half2_rn(fmaxf(acc[im][j][0] + b0, 0.f),
                                        fmaxf(acc[im][j][1] + b1, 0.f));
                __half2* p1 = reinterpret_cast<__half2*>(
                    dsm + (uint32_t)(ml + 8) * STG_STRIDE + nl * 2);
                *p1 = __floats2half2_rn(fmaxf(acc[im][j][2] + b0, 0.f),
                                        fmaxf(acc[im][j][3] + b1, 0.f));
            }
        }
        __syncthreads();
        __half* C = (__half*)Cout;
        #pragma unroll
        for (int p = 0; p < 16; p++) {
            int idx = tid + p * 256;
            int r = idx >> 5, u = idx & 31;
            int gm = row0 + r;
            if (gm < M) {
                uint4 v = *reinterpret_cast<const uint4*>(
                    dsm + (uint32_t)r * STG_STRIDE + u * 16);
                *reinterpret_cast<uint4*>(
                    C + (size_t)gm * Nreal + col0 + u * 8) = v;
            }
        }
    } else {
        #pragma unroll
        for (int im = 0; im < 2; im++) {
            int m0 = row0 + m_base + im * 16 + (lane >> 2);
            #pragma unroll
            for (int j = 0; j < 16; j++) {
                int n = col0 + n_base + j * 8 + (lane & 3) * 2;
                #pragma unroll
                for (int q = 0; q < 4; q++) {
                    int mm = m0 + (q >> 1) * 8;
                    int nn = n + (q & 1);
                    if (mm < M && nn < Nreal) {
                        float v = fmaxf(acc[im][j][q] + bias[nn], 0.f);
                        if (HALF_OUT)
                            ((__half*)Cout)[(size_t)mm * Nreal + nn] =
                                __float2half_rn(v);
                        else
                            ((float*)Cout)[(size_t)mm * Nreal + nn] = v;
                    }
                }
            }
        }
    }
}

// ===========================================================================
// Fused MLP2 + classifier: m2 = relu(m1@lw2 + lb2); out = m2@cw + cb
// ===========================================================================
#define BM 128
#define BN 128
#define BK8 8
#define TM 8
#define TN 8
#define MLP2_SMEM (BM * MLP2 * 4)   // 51200 B

__global__ __launch_bounds__(256)
void mlp2_cls_kernel(const float* __restrict__ A, const float* __restrict__ B,
                     const float* __restrict__ bias,
                     const float* __restrict__ cw, const float* __restrict__ cb,
                     float* __restrict__ out, int M, int N, int K) {
    extern __shared__ float sbuf[];
    float* As = sbuf;                 // [BK8][BM]
    float* Bs = sbuf + BK8 * BM;      // [BK8][BN]
    const int tid  = threadIdx.x;
    const int row0 = blockIdx.y * BM;
    const int tx = tid & 15;
    const int ty = tid >> 4;
    float acc[TM][TN];
    #pragma unroll
    for (int i = 0; i < TM; i++)
        #pragma unroll
        for (int j = 0; j < TN; j++) acc[i][j] = 0.f;

    for (int k0 = 0; k0 < K; k0 += BK8) {
        #pragma unroll
        for (int i = 0; i < 4; i++) {
            int idx = tid + i * 256;
            int m = idx >> 3, k = idx & 7;
            int gm = row0 + m, gk = k0 + k;
            As[k * BM + m] = (gm < M && gk < K) ? A[(size_t)gm * K + gk] : 0.f;
        }
        #pragma unroll
        for (int i = 0; i < 4; i++) {
            int idx = tid + i * 256;
            int k = idx >> 7, n = idx & 127;
            int gk = k0 + k;
            Bs[k * BN + n] = (gk < K && n < N) ? B[(size_t)gk * N + n] : 0.f;
        }
        __syncthreads();
        #pragma unroll
        for (int k = 0; k < BK8; k++) {
            float a[TM], b[TN];
            #pragma unroll
            for (int i = 0; i < TM; i++) a[i] = As[k * BM + ty * TM + i];
            #pragma unroll
            for (int j = 0; j < TN; j++) b[j] = Bs[k * BN + tx * TN + j];
            #pragma unroll
            for (int i = 0; i < TM; i++)
                #pragma unroll
                for (int j = 0; j < TN; j++)
                    acc[i][j] += a[i] * b[j];
        }
        __syncthreads();
    }

    // Stage relu(m2) tile in smem, then classifier dot in-block.
    float* sm2 = sbuf;   // [BM][MLP2]
    __syncthreads();
    #pragma unroll
    for (int i = 0; i < TM; i++) {
        int lm = ty * TM + i;
        #pragma unroll
        for (int j = 0; j < TN; j++) {
            int n = tx * TN + j;
            if (n < N)
                sm2[lm * MLP2 + n] = fmaxf(acc[i][j] + bias[n], 0.f);
        }
    }
    __syncthreads();
    if (tid < BM) {
        int gm = row0 + tid;
        if (gm < M) {
            float a0 = cb[0], a1 = cb[1];
            const float* row = sm2 + tid * MLP2;
            #pragma unroll 4
            for (int k = 0; k < MLP2; k++) {
                float v = row[k];
                a0 += v * cw[k * 2 + 0];
                a1 += v * cw[k * 2 + 1];
            }
            out[gm * 2 + 0] = a0;
            out[gm * 2 + 1] = a1;
        }
    }
}

// ===========================================================================
// Mean pool (sorted node2graph, fp16 input) + concat descriptors -> X fp16
// ===========================================================================
__device__ __forceinline__ int lower_bound_dev(const int* a, int n, int v) {
    int lo = 0, hi = n;
    while (lo < hi) {
        int m = (lo + hi) >> 1;
        if (a[m] < v) lo = m + 1; else hi = m;
    }
    return lo;
}
__global__ void pool_concat_kernel(const __half* __restrict__ h2,
                                   const float* __restrict__ desc,
                                   const int* __restrict__ n2g,
                                   __half* __restrict__ X) {
    int g = blockIdx.x;
    __shared__ int s_lo, s_hi;
    if (threadIdx.x == 0) s_lo = lower_bound_dev(n2g, N_NODES, g);
    if (threadIdx.x == 1) s_hi = lower_bound_dev(n2g, N_NODES, g + 1);
    __syncthreads();
    int lo = s_lo, hi = s_hi;
    float inv = 1.f / fmaxf((float)(hi - lo), 1.f);
    int t = threadIdx.x;
    float2 a0 = make_float2(0.f, 0.f), a1 = make_float2(0.f, 0.f);
    for (int i = lo; i < hi; i++) {
        const __half2* row = reinterpret_cast<const __half2*>(
            h2 + (size_t)i * HID);
        float2 v0 = __half22float2(row[t * 2 + 0]);
        float2 v1 = __half22float2(row[t * 2 + 1]);
        a0.x += v0.x; a0.y += v0.y;
        a1.x += v1.x; a1.y += v1.y;
    }
    size_t rb = (size_t)g * XPAD;
    __half2* xrow = reinterpret_cast<__half2*>(X + rb);
    xrow[t * 2 + 0] = __floats2half2_rn(a0.x * inv, a0.y * inv);
    xrow[t * 2 + 1] = __floats2half2_rn(a1.x * inv, a1.y * inv);
    for (int d = t; d < N_DESC; d += 128)
        X[rb + HID + d] = __float2half_rn(desc[(size_t)g * N_DESC + d]);
    for (int d = t; d < XPAD - XDIM; d += 128)
        X[rb + XDIM + d] = __float2half_rn(0.f);
}

// ===========================================================================
// Launch
// ===========================================================================
extern "C" void kernel_launch(void* const* d_in, const int* in_sizes, int n_in,
                              void* d_out, int out_size) {
    const float* features    = (const float*)d_in[0];
    const float* descriptors = (const float*)d_in[1];
    const int*   src         = (const int*)  d_in[2];
    const int*   dst         = (const int*)  d_in[3];
    const int*   n2g         = (const int*)  d_in[4];
    const float* W1          = (const float*)d_in[5];
    const float* b1          = (const float*)d_in[6];
    const float* W2          = (const float*)d_in[7];
    const float* b2          = (const float*)d_in[8];
    const float* lw1         = (const float*)d_in[9];
    const float* lb1         = (const float*)d_in[10];
    const float* lw2         = (const float*)d_in[11];
    const float* lb2         = (const float*)d_in[12];
    const float* cw          = (const float*)d_in[13];
    const float* cb          = (const float*)d_in[14];
    float* out = (float*)d_out;

    __half *a0, *h1, *a1, *h2, *X, *B1, *B2, *BL;
    float *m1;
    cudaGetSymbolAddress((void**)&a0, g_a0);
    cudaGetSymbolAddress((void**)&h1, g_h1);
    cudaGetSymbolAddress((void**)&a1, g_a1);
    cudaGetSymbolAddress((void**)&h2, g_h2);
    cudaGetSymbolAddress((void**)&X,  g_X);
    cudaGetSymbolAddress((void**)&m1, g_m1);
    cudaGetSymbolAddress((void**)&B1, g_B1);
    cudaGetSymbolAddress((void**)&B2, g_B2);
    cudaGetSymbolAddress((void**)&BL, g_BL);

    cudaFuncSetAttribute(gemm_fp16<true>,
                         cudaFuncAttributeMaxDynamicSharedMemorySize, GDSM);
    cudaFuncSetAttribute(gemm_fp16<false>,
                         cudaFuncAttributeMaxDynamicSharedMemorySize, GDSM);
    cudaFuncSetAttribute(mlp2_cls_kernel,
                         cudaFuncAttributeMaxDynamicSharedMemorySize, MLP2_SMEM);

    // init (zero deg + zero scan state + weight prep)
    init_kernel<<<(INIT_TOTAL + 255) / 256, 256>>>(W1, W2, lw1, B1, B2, BL);
    // CSR build (count -> single-pass lookback scan -> fill)
    count_deg_kernel<<<(N_EDGES + 255) / 256, 256>>>(dst);
    scan_lookback_kernel<<<NSCAN_BLOCKS, 256>>>();
    fill_csr_kernel<<<(N_EDGES + 255) / 256, 256>>>(src, dst);

    // Layer 1
    gather_sum_128<<<N_NODES / 8, 256>>>(features, a0);
    { dim3 g(2, (N_NODES + 127) / 128);
      gemm_fp16<true><<<g, 256, GDSM>>>(a0, B1, b1, h1, N_NODES, HID, IN_DIM); }

    // Layer 2
    gather_sum_512h<<<N_NODES / 4, 256>>>(h1, a1);
    { dim3 g(2, (N_NODES + 127) / 128);
      gemm_fp16<true><<<g, 256, GDSM>>>(a1, B2, b2, h2, N_NODES, HID, HID); }

    // Pool + concat
    pool_concat_kernel<<<N_GRAPHS, 128>>>(h2, descriptors, n2g, X);

    // MLP head
    { dim3 g(2, (N_GRAPHS + 127) / 128);
      gemm_fp16<false><<<g, 256, GDSM>>>(X, BL, lb1, m1, N_GRAPHS, MLP1, XPAD); }
    { dim3 g(1, (N_GRAPHS + 127) / 128);
      mlp2_cls_kernel<<<g, 256, MLP2_SMEM>>>(m1, lw2, lb2, cw, cb, out,
                                             N_GRAPHS, MLP2, MLP1); }
}

// round 16
// speedup vs baseline: 1.0231x; 1.0231x over previous
#include <cuda_runtime.h>
#include <cuda_fp16.h>
#include <cstdint>
#include <cstddef>

// Problem constants
#define N_NODES  100000
#define N_EDGES  400000
#define N_GRAPHS 4000
#define IN_DIM   128
#define HID      512
#define N_DESC   200
#define XDIM     (HID + N_DESC)   // 712
#define XPAD     768              // multiple of 64 (BK)
#define MLP1     500
#define MLP1PAD  512
#define MLP2     100
#define NSCAN_BLOCKS ((N_NODES + 255) / 256)   // 391

// ===========================================================================
// PTX helpers (plain sm_80-era features only)
// ===========================================================================
__device__ __forceinline__ uint32_t smem_to_u32(const void* p) {
    uint32_t a;
    asm("{ .reg .u64 t; cvta.to.shared.u64 t, %1; cvt.u32.u64 %0, t; }"
        : "=r"(a) : "l"(p));
    return a;
}
__device__ __forceinline__ void ldsm_x4(uint32_t& r0, uint32_t& r1,
                                        uint32_t& r2, uint32_t& r3,
                                        uint32_t addr) {
    asm volatile("ldmatrix.sync.aligned.m8n8.x4.shared.b16 {%0,%1,%2,%3}, [%4];"
                 : "=r"(r0), "=r"(r1), "=r"(r2), "=r"(r3) : "r"(addr));
}
__device__ __forceinline__ void mma_fp16(float* c, const uint32_t* a,
                                         uint32_t b0, uint32_t b1) {
    asm volatile(
        "mma.sync.aligned.m16n8k16.row.col.f32.f16.f16.f32 "
        "{%0,%1,%2,%3}, {%4,%5,%6,%7}, {%8,%9}, {%0,%1,%2,%3};"
        : "+f"(c[0]), "+f"(c[1]), "+f"(c[2]), "+f"(c[3])
        : "r"(a[0]), "r"(a[1]), "r"(a[2]), "r"(a[3]), "r"(b0), "r"(b1));
}
__device__ __forceinline__ void cpa16(uint32_t s, const void* g, uint32_t sz) {
    asm volatile("cp.async.cg.shared.global [%0], [%1], 16, %2;"
                 :: "r"(s), "l"(g), "r"(sz));
}
#define CP_COMMIT() asm volatile("cp.async.commit_group;" ::: "memory")
#define CP_WAIT(n)  asm volatile("cp.async.wait_group %0;" :: "n"(n) : "memory")

// ===========================================================================
// Device scratch
// ===========================================================================
__device__ __align__(16) int g_deg[N_NODES];
__device__ __align__(16) int g_off[N_NODES + 4];
__device__ __align__(16) int g_cur[N_NODES];
__device__ int g_csr[N_EDGES];
__device__ int g_bsum[NSCAN_BLOCKS + 1];

__device__ __half g_a0 [(size_t)N_NODES * IN_DIM];
__device__ __half g_h1 [(size_t)N_NODES * HID];
__device__ __half g_a1 [(size_t)N_NODES * HID];
__device__ __half g_h2 [(size_t)N_NODES * HID];
__device__ __half g_X  [(size_t)N_GRAPHS * XPAD];
__device__ float  g_m1 [(size_t)N_GRAPHS * MLP1];

// Weight images: B^T fp16, [Npad][Kpad], k-contiguous
__device__ __half g_B1[512 * 128];
__device__ __half g_B2[512 * 512];
__device__ __half g_BL[MLP1PAD * XPAD];

// ===========================================================================
// Fused init: zero g_deg + prep all three weight images
// ===========================================================================
#define Z0 (N_NODES)
#define Z1 (512 * 128)
#define Z2 (512 * 512)
#define Z3 (MLP1PAD * XPAD)
#define INIT_TOTAL (Z0 + Z1 + Z2 + Z3)

__device__ __forceinline__ void prep_one(const float* __restrict__ W,
                                         __half* __restrict__ B,
                                         int local, int K_real, int N_real,
                                         int Kpad) {
    int n = local / Kpad, k = local % Kpad;
    float v = (k < K_real && n < N_real) ? W[(size_t)k * N_real + n] : 0.f;
    B[local] = __float2half_rn(v);
}

__global__ void init_kernel(const float* __restrict__ W1,
                            const float* __restrict__ W2,
                            const float* __restrict__ lw1,
                            __half* __restrict__ B1, __half* __restrict__ B2,
                            __half* __restrict__ BL) {
    int idx = blockIdx.x * blockDim.x + threadIdx.x;
    if (idx < Z0) {
        g_deg[idx] = 0;
    } else if (idx < Z0 + Z1) {
        prep_one(W1, B1, idx - Z0, IN_DIM, HID, 128);
    } else if (idx < Z0 + Z1 + Z2) {
        prep_one(W2, B2, idx - Z0 - Z1, HID, HID, 512);
    } else if (idx < INIT_TOTAL) {
        prep_one(lw1, BL, idx - Z0 - Z1 - Z2, XDIM, MLP1, XPAD);
    }
}

// ===========================================================================
// CSR construction: count -> partial sums -> apply (self prefix) -> fill
// ===========================================================================
__global__ void count_deg_kernel(const int* __restrict__ dst) {
    int e = blockIdx.x * blockDim.x + threadIdx.x;
    if (e < N_EDGES) atomicAdd(&g_deg[dst[e]], 1);
}

__global__ __launch_bounds__(256)
void scan_partial_kernel() {
    __shared__ int red[8];
    int i = blockIdx.x * 256 + threadIdx.x;
    int v = (i < N_NODES) ? g_deg[i] : 0;
    #pragma unroll
    for (int o = 16; o > 0; o >>= 1)
        v += __shfl_down_sync(0xFFFFFFFF, v, o);
    if ((threadIdx.x & 31) == 0) red[threadIdx.x >> 5] = v;
    __syncthreads();
    if (threadIdx.x < 8) {
        int s = red[threadIdx.x];
        #pragma unroll
        for (int o = 4; o > 0; o >>= 1)
            s += __shfl_down_sync(0xFF, s, o);
        if (threadIdx.x == 0) g_bsum[blockIdx.x] = s;
    }
}

// Apply: each block computes its own prefix over g_bsum (L2-hot, 391 ints),
// then intra-block scan, writes g_off/g_cur (+ g_off[N_NODES] by last block).
__global__ __launch_bounds__(256)
void scan_apply_kernel() {
    __shared__ int part[256];
    __shared__ int wsum[8];
    __shared__ int s_base;
    const int t = threadIdx.x;
    const int b = blockIdx.x;

    int p = 0;
    for (int i = t; i < b; i += 256) p += g_bsum[i];
    #pragma unroll
    for (int o = 16; o > 0; o >>= 1)
        p += __shfl_down_sync(0xFFFFFFFF, p, o);
    if ((t & 31) == 0) wsum[t >> 5] = p;
    __syncthreads();
    if (t == 0) {
        int s = 0;
        #pragma unroll
        for (int w = 0; w < 8; w++) s += wsum[w];
        s_base = s;
    }

    int i = b * 256 + t;
    int d = (i < N_NODES) ? g_deg[i] : 0;
    part[t] = d;
    __syncthreads();
    for (int off = 1; off < 256; off <<= 1) {
        int v = (t >= off) ? part[t - off] : 0;
        __syncthreads();
        part[t] += v;
        __syncthreads();
    }
    int base = s_base;
    if (i < N_NODES) {
        int off = base + part[t] - d;   // exclusive
        g_off[i] = off;
        g_cur[i] = off;
    }
    if (b == NSCAN_BLOCKS - 1 && t == 255)
        g_off[N_NODES] = base + part[255];
}

__global__ void fill_csr_kernel(const int* __restrict__ src,
                                const int* __restrict__ dst) {
    int e = blockIdx.x * blockDim.x + threadIdx.x;
    if (e < N_EDGES) {
        int p = atomicAdd(&g_cur[dst[e]], 1);
        g_csr[p] = src[e];
    }
}

// ===========================================================================
// Gather-sum kernels: R7 thread structure + 2-deep software pipeline
// ===========================================================================
// fp32 features, 32 threads/node (float4), 8 nodes/block.
__global__ __launch_bounds__(256)
void gather_sum_128(const float* __restrict__ feat, __half* __restrict__ o) {
    int n = blockIdx.x * 8 + (threadIdx.x >> 5);
    int t = threadIdx.x & 31;
    int lo = g_off[n], hi = g_off[n + 1];
    float4 acc = make_float4(0.f, 0.f, 0.f, 0.f);
    int j = lo;
    if (j < hi) {
        float4 cur = reinterpret_cast<const float4*>(
            feat + (size_t)g_csr[j] * IN_DIM)[t];
        for (++j; j < hi; ++j) {
            float4 nxt = reinterpret_cast<const float4*>(
                feat + (size_t)g_csr[j] * IN_DIM)[t];
            acc.x += cur.x; acc.y += cur.y; acc.z += cur.z; acc.w += cur.w;
            cur = nxt;
        }
        acc.x += cur.x; acc.y += cur.y; acc.z += cur.z; acc.w += cur.w;
    }
    __half2 h0 = __floats2half2_rn(acc.x, acc.y);
    __half2 h1v = __floats2half2_rn(acc.z, acc.w);
    __half2* op = reinterpret_cast<__half2*>(o + (size_t)n * IN_DIM) + t * 2;
    op[0] = h0;
    op[1] = h1v;
}

// h fp16, 64 threads/node (uint4), 4 nodes/block.
__global__ __launch_bounds__(256)
void gather_sum_512h(const __half* __restrict__ h, __half* __restrict__ o) {
    int n = blockIdx.x * 4 + (threadIdx.x >> 6);
    int t = threadIdx.x & 63;
    int lo = g_off[n], hi = g_off[n + 1];
    float acc[8];
    #pragma unroll
    for (int i = 0; i < 8; i++) acc[i] = 0.f;
    int j = lo;
    if (j < hi) {
        uint4 cur = reinterpret_cast<const uint4*>(
            h + (size_t)g_csr[j] * HID)[t];
        for (++j; j < hi; ++j) {
            uint4 nxt = reinterpret_cast<const uint4*>(
                h + (size_t)g_csr[j] * HID)[t];
            const __half2* hp = reinterpret_cast<const __half2*>(&cur);
            #pragma unroll
            for (int i = 0; i < 4; i++) {
                float2 v = __half22float2(hp[i]);
                acc[i * 2 + 0] += v.x;
                acc[i * 2 + 1] += v.y;
            }
            cur = nxt;
        }
        const __half2* hp = reinterpret_cast<const __half2*>(&cur);
        #pragma unroll
        for (int i = 0; i < 4; i++) {
            float2 v = __half22float2(hp[i]);
            acc[i * 2 + 0] += v.x;
            acc[i * 2 + 1] += v.y;
        }
    }
    uint4 out;
    __half2* op = reinterpret_cast<__half2*>(&out);
    #pragma unroll
    for (int i = 0; i < 4; i++)
        op[i] = __floats2half2_rn(acc[i * 2], acc[i * 2 + 1]);
    reinterpret_cast<uint4*>(o + (size_t)n * HID)[t] = out;
}

// ===========================================================================
// fp16 tensor-core GEMM (R7-exact): C[M,Nreal] = relu(A@W + bias)
// CTA 128m x 256n, BK=64, 8 warps (32m x 128n), 2-stage cp.async.
// 144B smem rows -> conflict-free ldmatrix; smem-staged coalesced epilogue.
// ===========================================================================
#define GROW  144u
#define ATILE 18432u
#define GBUF  55296u
#define GDSM  (2 * GBUF)
#define STG_STRIDE 528u

template <bool HALF_OUT>
__global__ __launch_bounds__(256, 1)
void gemm_fp16(const __half* __restrict__ A, const __half* __restrict__ B,
               const float* __restrict__ bias, void* __restrict__ Cout,
               int M, int Nreal, int K)
{
    extern __shared__ char dsm[];
    const uint32_t sbase = smem_to_u32(dsm);
    const int tid  = threadIdx.x;
    const int lane = tid & 31;
    const int wid  = tid >> 5;
    const int row0 = blockIdx.y * 128;
    const int col0 = blockIdx.x * 256;
    const int NC   = K / 64;

    const int m_base = (wid & 3) * 32;
    const int n_base = (wid >> 2) * 128;

    float acc[2][16][4];
    #pragma unroll
    for (int i = 0; i < 2; i++)
        #pragma unroll
        for (int j = 0; j < 16; j++)
            #pragma unroll
            for (int q = 0; q < 4; q++) acc[i][j][q] = 0.f;

    auto load_chunk = [&](int buf, int c) {
        uint32_t s = sbase + (uint32_t)buf * GBUF;
        #pragma unroll
        for (int i = 0; i < 4; i++) {
            int f  = tid + i * 256;
            int m  = f >> 3, k8 = f & 7;
            int gm = row0 + m;
            uint32_t ok = (gm < M) ? 16u : 0u;
            int gmc = (gm < M) ? gm : 0;
            cpa16(s + m * GROW + k8 * 16,
                  A + (size_t)gmc * K + c * 64 + k8 * 8, ok);
        }
        #pragma unroll
        for (int i = 0; i < 8; i++) {
            int f = tid + i * 256;
            int n = f >> 3, k8 = f & 7;
            cpa16(s + ATILE + n * GROW + k8 * 16,
                  B + (size_t)(col0 + n) * K + c * 64 + k8 * 8, 16u);
        }
        CP_COMMIT();
    };

    load_chunk(0, 0);

    for (int c = 0; c < NC; c++) {
        const int buf = c & 1;
        if (c + 1 < NC) {
            load_chunk(buf ^ 1, c + 1);
            CP_WAIT(1);
        } else {
            CP_WAIT(0);
        }
        __syncthreads();

        const uint32_t sA = sbase + (uint32_t)buf * GBUF;
        const uint32_t sB = sA + ATILE;

        #pragma unroll
        for (int ks = 0; ks < 4; ks++) {
            uint32_t a[2][4];
            #pragma unroll
            for (int im = 0; im < 2; im++) {
                uint32_t ra = sA
                    + (uint32_t)(m_base + im * 16 + (lane & 15)) * GROW
                    + (uint32_t)(ks * 16 + ((lane >> 4) * 8)) * 2;
                ldsm_x4(a[im][0], a[im][1], a[im][2], a[im][3], ra);
            }
            #pragma unroll
            for (int g = 0; g < 8; g++) {
                uint32_t bh[4];
                uint32_t rb = sB
                    + (uint32_t)(n_base + g * 16 +
                                 ((lane >> 4) & 1) * 8 + (lane & 7)) * GROW
                    + (uint32_t)(ks * 16 + ((lane >> 3) & 1) * 8) * 2;
                ldsm_x4(bh[0], bh[1], bh[2], bh[3], rb);
                #pragma unroll
                for (int im = 0; im < 2; im++) {
                    #pragma unroll
                    for (int sub = 0; sub < 2; sub++) {
                        mma_fp16(acc[im][g * 2 + sub], a[im],
                                 bh[sub * 2], bh[sub * 2 + 1]);
                    }
                }
            }
        }
        __syncthreads();
    }

    const bool full_n = (col0 + 256 <= Nreal);
    if (HALF_OUT && full_n) {
        #pragma unroll
        for (int im = 0; im < 2; im++) {
            int ml = m_base + im * 16 + (lane >> 2);
            #pragma unroll
            for (int j = 0; j < 16; j++) {
                int nl = n_base + j * 8 + (lane & 3) * 2;
                float b0 = bias[col0 + nl], b1 = bias[col0 + nl + 1];
                __half2* p0 = reinterpret_cast<__half2*>(
                    dsm + (uint32_t)ml * STG_STRIDE + nl * 2);
                *p0 = __floats2half2_rn(fmaxf(acc[im][j][0] + b0, 0.f),
                                        fmaxf(acc[im][j][1] + b1, 0.f));
                __half2* p1 = reinterpret_cast<__half2*>(
                    dsm + (uint32_t)(ml + 8) * STG_STRIDE + nl * 2);
                *p1 = __floats2half2_rn(fmaxf(acc[im][j][2] + b0, 0.f),
                                        fmaxf(acc[im][j][3] + b1, 0.f));
            }
        }
        __syncthreads();
        __half* C = (__half*)Cout;
        #pragma unroll
        for (int p = 0; p < 16; p++) {
            int idx = tid + p * 256;
            int r = idx >> 5, u = idx & 31;
            int gm = row0 + r;
            if (gm < M) {
                uint4 v = *reinterpret_cast<const uint4*>(
                    dsm + (uint32_t)r * STG_STRIDE + u * 16);
                *reinterpret_cast<uint4*>(
                    C + (size_t)gm * Nreal + col0 + u * 8) = v;
            }
        }
    } else {
        #pragma unroll
        for (int im = 0; im < 2; im++) {
            int m0 = row0 + m_base + im * 16 + (lane >> 2);
            #pragma unroll
            for (int j = 0; j < 16; j++) {
                int n = col0 + n_base + j * 8 + (lane & 3) * 2;
                #pragma unroll
                for (int q = 0; q < 4; q++) {
                    int mm = m0 + (q >> 1) * 8;
                    int nn = n + (q & 1);
                    if (mm < M && nn < Nreal) {
                        float v = fmaxf(acc[im][j][q] + bias[nn], 0.f);
                        if (HALF_OUT)
                            ((__half*)Cout)[(size_t)mm * Nreal + nn] =
                                __float2half_rn(v);
                        else
                            ((float*)Cout)[(size_t)mm * Nreal + nn] = v;
                    }
                }
            }
        }
    }
}

// ===========================================================================
// Fused MLP2 + classifier: m2 = relu(m1@lw2 + lb2); out = m2@cw + cb
// ===========================================================================
#define BM 128
#define BN 128
#define BK8 8
#define TM 8
#define TN 8
#define MLP2_SMEM (BM * MLP2 * 4)   // 51200 B

__global__ __launch_bounds__(256)
void mlp2_cls_kernel(const float* __restrict__ A, const float* __restrict__ B,
                     const float* __restrict__ bias,
                     const float* __restrict__ cw, const float* __restrict__ cb,
                     float* __restrict__ out, int M, int N, int K) {
    extern __shared__ float sbuf[];
    float* As = sbuf;                 // [BK8][BM]
    float* Bs = sbuf + BK8 * BM;      // [BK8][BN]
    const int tid  = threadIdx.x;
    const int row0 = blockIdx.y * BM;
    const int tx = tid & 15;
    const int ty = tid >> 4;
    float acc[TM][TN];
    #pragma unroll
    for (int i = 0; i < TM; i++)
        #pragma unroll
        for (int j = 0; j < TN; j++) acc[i][j] = 0.f;

    for (int k0 = 0; k0 < K; k0 += BK8) {
        #pragma unroll
        for (int i = 0; i < 4; i++) {
            int idx = tid + i * 256;
            int m = idx >> 3, k = idx & 7;
            int gm = row0 + m, gk = k0 + k;
            As[k * BM + m] = (gm < M && gk < K) ? A[(size_t)gm * K + gk] : 0.f;
        }
        #pragma unroll
        for (int i = 0; i < 4; i++) {
            int idx = tid + i * 256;
            int k = idx >> 7, n = idx & 127;
            int gk = k0 + k;
            Bs[k * BN + n] = (gk < K && n < N) ? B[(size_t)gk * N + n] : 0.f;
        }
        __syncthreads();
        #pragma unroll
        for (int k = 0; k < BK8; k++) {
            float a[TM], b[TN];
            #pragma unroll
            for (int i = 0; i < TM; i++) a[i] = As[k * BM + ty * TM + i];
            #pragma unroll
            for (int j = 0; j < TN; j++) b[j] = Bs[k * BN + tx * TN + j];
            #pragma unroll
            for (int i = 0; i < TM; i++)
                #pragma unroll
                for (int j = 0; j < TN; j++)
                    acc[i][j] += a[i] * b[j];
        }
        __syncthreads();
    }

    // Stage relu(m2) tile in smem, then classifier dot in-block.
    float* sm2 = sbuf;   // [BM][MLP2]
    __syncthreads();
    #pragma unroll
    for (int i = 0; i < TM; i++) {
        int lm = ty * TM + i;
        #pragma unroll
        for (int j = 0; j < TN; j++) {
            int n = tx * TN + j;
            if (n < N)
                sm2[lm * MLP2 + n] = fmaxf(acc[i][j] + bias[n], 0.f);
        }
    }
    __syncthreads();
    if (tid < BM) {
        int gm = row0 + tid;
        if (gm < M) {
            float a0 = cb[0], a1 = cb[1];
            const float* row = sm2 + tid * MLP2;
            #pragma unroll 4
            for (int k = 0; k < MLP2; k++) {
                float v = row[k];
                a0 += v * cw[k * 2 + 0];
                a1 += v * cw[k * 2 + 1];
            }
            out[gm * 2 + 0] = a0;
            out[gm * 2 + 1] = a1;
        }
    }
}

// ===========================================================================
// Mean pool (sorted node2graph, fp16 input) + concat descriptors -> X fp16
// ===========================================================================
__device__ __forceinline__ int lower_bound_dev(const int* a, int n, int v) {
    int lo = 0, hi = n;
    while (lo < hi) {
        int m = (lo + hi) >> 1;
        if (a[m] < v) lo = m + 1; else hi = m;
    }
    return lo;
}
__global__ void pool_concat_kernel(const __half* __restrict__ h2,
                                   const float* __restrict__ desc,
                                   const int* __restrict__ n2g,
                                   __half* __restrict__ X) {
    int g = blockIdx.x;
    __shared__ int s_lo, s_hi;
    if (threadIdx.x == 0) s_lo = lower_bound_dev(n2g, N_NODES, g);
    if (threadIdx.x == 1) s_hi = lower_bound_dev(n2g, N_NODES, g + 1);
    __syncthreads();
    int lo = s_lo, hi = s_hi;
    float inv = 1.f / fmaxf((float)(hi - lo), 1.f);
    int t = threadIdx.x;
    float2 a0 = make_float2(0.f, 0.f), a1 = make_float2(0.f, 0.f);
    for (int i = lo; i < hi; i++) {
        const __half2* row = reinterpret_cast<const __half2*>(
            h2 + (size_t)i * HID);
        float2 v0 = __half22float2(row[t * 2 + 0]);
        float2 v1 = __half22float2(row[t * 2 + 1]);
        a0.x += v0.x; a0.y += v0.y;
        a1.x += v1.x; a1.y += v1.y;
    }
    size_t rb = (size_t)g * XPAD;
    __half2* xrow = reinterpret_cast<__half2*>(X + rb);
    xrow[t * 2 + 0] = __floats2half2_rn(a0.x * inv, a0.y * inv);
    xrow[t * 2 + 1] = __floats2half2_rn(a1.x * inv, a1.y * inv);
    for (int d = t; d < N_DESC; d += 128)
        X[rb + HID + d] = __float2half_rn(desc[(size_t)g * N_DESC + d]);
    for (int d = t; d < XPAD - XDIM; d += 128)
        X[rb + XDIM + d] = __float2half_rn(0.f);
}

// ===========================================================================
// Launch
// ===========================================================================
extern "C" void kernel_launch(void* const* d_in, const int* in_sizes, int n_in,
                              void* d_out, int out_size) {
    const float* features    = (const float*)d_in[0];
    const float* descriptors = (const float*)d_in[1];
    const int*   src         = (const int*)  d_in[2];
    const int*   dst         = (const int*)  d_in[3];
    const int*   n2g         = (const int*)  d_in[4];
    const float* W1          = (const float*)d_in[5];
    const float* b1          = (const float*)d_in[6];
    const float* W2          = (const float*)d_in[7];
    const float* b2          = (const float*)d_in[8];
    const float* lw1         = (const float*)d_in[9];
    const float* lb1         = (const float*)d_in[10];
    const float* lw2         = (const float*)d_in[11];
    const float* lb2         = (const float*)d_in[12];
    const float* cw          = (const float*)d_in[13];
    const float* cb          = (const float*)d_in[14];
    float* out = (float*)d_out;

    __half *a0, *h1, *a1, *h2, *X, *B1, *B2, *BL;
    float *m1;
    cudaGetSymbolAddress((void**)&a0, g_a0);
    cudaGetSymbolAddress((void**)&h1, g_h1);
    cudaGetSymbolAddress((void**)&a1, g_a1);
    cudaGetSymbolAddress((void**)&h2, g_h2);
    cudaGetSymbolAddress((void**)&X,  g_X);
    cudaGetSymbolAddress((void**)&m1, g_m1);
    cudaGetSymbolAddress((void**)&B1, g_B1);
    cudaGetSymbolAddress((void**)&B2, g_B2);
    cudaGetSymbolAddress((void**)&BL, g_BL);

    cudaFuncSetAttribute(gemm_fp16<true>,
                         cudaFuncAttributeMaxDynamicSharedMemorySize, GDSM);
    cudaFuncSetAttribute(gemm_fp16<false>,
                         cudaFuncAttributeMaxDynamicSharedMemorySize, GDSM);
    cudaFuncSetAttribute(mlp2_cls_kernel,
                         cudaFuncAttributeMaxDynamicSharedMemorySize, MLP2_SMEM);

    // init (zero deg + weight prep)
    init_kernel<<<(INIT_TOTAL + 255) / 256, 256>>>(W1, W2, lw1, B1, B2, BL);
    // CSR build
    count_deg_kernel<<<(N_EDGES + 255) / 256, 256>>>(dst);
    scan_partial_kernel<<<NSCAN_BLOCKS, 256>>>();
    scan_apply_kernel<<<NSCAN_BLOCKS, 256>>>();
    fill_csr_kernel<<<(N_EDGES + 255) / 256, 256>>>(src, dst);

    // Layer 1
    gather_sum_128<<<N_NODES / 8, 256>>>(features, a0);
    { dim3 g(2, (N_NODES + 127) / 128);
      gemm_fp16<true><<<g, 256, GDSM>>>(a0, B1, b1, h1, N_NODES, HID, IN_DIM); }

    // Layer 2
    gather_sum_512h<<<N_NODES / 4, 256>>>(h1, a1);
    { dim3 g(2, (N_NODES + 127) / 128);
      gemm_fp16<true><<<g, 256, GDSM>>>(a1, B2, b2, h2, N_NODES, HID, HID); }

    // Pool + concat
    pool_concat_kernel<<<N_GRAPHS, 128>>>(h2, descriptors, n2g, X);

    // MLP head
    { dim3 g(2, (N_GRAPHS + 127) / 128);
      gemm_fp16<false><<<g, 256, GDSM>>>(X, BL, lb1, m1, N_GRAPHS, MLP1, XPAD); }
    { dim3 g(1, (N_GRAPHS + 127) / 128);
      mlp2_cls_kernel<<<g, 256, MLP2_SMEM>>>(m1, lw2, lb2, cw, cb, out,
                                             N_GRAPHS, MLP2, MLP1); }
}

// round 17
// speedup vs baseline: 1.0406x; 1.0171x over previous
#include <cuda_runtime.h>
#include <cuda_fp16.h>
#include <cstdint>
#include <cstddef>

// Problem constants
#define N_NODES  100000
#define N_EDGES  400000
#define N_GRAPHS 4000
#define IN_DIM   128
#define HID      512
#define N_DESC   200
#define XDIM     (HID + N_DESC)   // 712
#define XPAD     768              // multiple of 64 (BK)
#define MLP1     500
#define MLP1PAD  512
#define MLP2     100
#define NSCAN_BLOCKS ((N_NODES + 255) / 256)   // 391

// ===========================================================================
// PTX helpers (plain sm_80-era features only)
// ===========================================================================
__device__ __forceinline__ uint32_t smem_to_u32(const void* p) {
    uint32_t a;
    asm("{ .reg .u64 t; cvta.to.shared.u64 t, %1; cvt.u32.u64 %0, t; }"
        : "=r"(a) : "l"(p));
    return a;
}
__device__ __forceinline__ void ldsm_x4(uint32_t& r0, uint32_t& r1,
                                        uint32_t& r2, uint32_t& r3,
                                        uint32_t addr) {
    asm volatile("ldmatrix.sync.aligned.m8n8.x4.shared.b16 {%0,%1,%2,%3}, [%4];"
                 : "=r"(r0), "=r"(r1), "=r"(r2), "=r"(r3) : "r"(addr));
}
__device__ __forceinline__ void mma_fp16(float* c, const uint32_t* a,
                                         uint32_t b0, uint32_t b1) {
    asm volatile(
        "mma.sync.aligned.m16n8k16.row.col.f32.f16.f16.f32 "
        "{%0,%1,%2,%3}, {%4,%5,%6,%7}, {%8,%9}, {%0,%1,%2,%3};"
        : "+f"(c[0]), "+f"(c[1]), "+f"(c[2]), "+f"(c[3])
        : "r"(a[0]), "r"(a[1]), "r"(a[2]), "r"(a[3]), "r"(b0), "r"(b1));
}
__device__ __forceinline__ void cpa16(uint32_t s, const void* g, uint32_t sz) {
    asm volatile("cp.async.cg.shared.global [%0], [%1], 16, %2;"
                 :: "r"(s), "l"(g), "r"(sz));
}
#define CP_COMMIT() asm volatile("cp.async.commit_group;" ::: "memory")
#define CP_WAIT(n)  asm volatile("cp.async.wait_group %0;" :: "n"(n) : "memory")

// ===========================================================================
// Device scratch
// ===========================================================================
__device__ __align__(16) int g_deg[N_NODES];
__device__ __align__(16) int g_off[N_NODES + 4];
__device__ __align__(16) int g_cur[N_NODES];
__device__ int g_csr[N_EDGES];
__device__ int g_bsum[NSCAN_BLOCKS + 1];

__device__ __half g_a0 [(size_t)N_NODES * IN_DIM];
__device__ __half g_h1 [(size_t)N_NODES * HID];
__device__ __half g_a1 [(size_t)N_NODES * HID];
__device__ __half g_h2 [(size_t)N_NODES * HID];
__device__ __half g_X  [(size_t)N_GRAPHS * XPAD];
__device__ float  g_m1 [(size_t)N_GRAPHS * MLP1];

// Weight images: B^T fp16, [Npad][Kpad], k-contiguous
__device__ __half g_B1[512 * 128];
__device__ __half g_B2[512 * 512];
__device__ __half g_BL[MLP1PAD * XPAD];

// ===========================================================================
// Fused init: zero g_deg + prep all three weight images
// ===========================================================================
#define Z0 (N_NODES)
#define Z1 (512 * 128)
#define Z2 (512 * 512)
#define Z3 (MLP1PAD * XPAD)
#define INIT_TOTAL (Z0 + Z1 + Z2 + Z3)

__device__ __forceinline__ void prep_one(const float* __restrict__ W,
                                         __half* __restrict__ B,
                                         int local, int K_real, int N_real,
                                         int Kpad) {
    int n = local / Kpad, k = local % Kpad;
    float v = (k < K_real && n < N_real) ? W[(size_t)k * N_real + n] : 0.f;
    B[local] = __float2half_rn(v);
}

__global__ void init_kernel(const float* __restrict__ W1,
                            const float* __restrict__ W2,
                            const float* __restrict__ lw1,
                            __half* __restrict__ B1, __half* __restrict__ B2,
                            __half* __restrict__ BL) {
    int idx = blockIdx.x * blockDim.x + threadIdx.x;
    if (idx < Z0) {
        g_deg[idx] = 0;
    } else if (idx < Z0 + Z1) {
        prep_one(W1, B1, idx - Z0, IN_DIM, HID, 128);
    } else if (idx < Z0 + Z1 + Z2) {
        prep_one(W2, B2, idx - Z0 - Z1, HID, HID, 512);
    } else if (idx < INIT_TOTAL) {
        prep_one(lw1, BL, idx - Z0 - Z1 - Z2, XDIM, MLP1, XPAD);
    }
}

// ===========================================================================
// CSR construction: count -> partial sums -> apply (self prefix) -> fill
// ===========================================================================
__global__ void count_deg_kernel(const int* __restrict__ dst) {
    int e = blockIdx.x * blockDim.x + threadIdx.x;
    if (e < N_EDGES) atomicAdd(&g_deg[dst[e]], 1);
}

__global__ __launch_bounds__(256)
void scan_partial_kernel() {
    __shared__ int red[8];
    int i = blockIdx.x * 256 + threadIdx.x;
    int v = (i < N_NODES) ? g_deg[i] : 0;
    #pragma unroll
    for (int o = 16; o > 0; o >>= 1)
        v += __shfl_down_sync(0xFFFFFFFF, v, o);
    if ((threadIdx.x & 31) == 0) red[threadIdx.x >> 5] = v;
    __syncthreads();
    if (threadIdx.x < 8) {
        int s = red[threadIdx.x];
        #pragma unroll
        for (int o = 4; o > 0; o >>= 1)
            s += __shfl_down_sync(0xFF, s, o);
        if (threadIdx.x == 0) g_bsum[blockIdx.x] = s;
    }
}

__global__ __launch_bounds__(256)
void scan_apply_kernel() {
    __shared__ int part[256];
    __shared__ int wsum[8];
    __shared__ int s_base;
    const int t = threadIdx.x;
    const int b = blockIdx.x;

    int p = 0;
    for (int i = t; i < b; i += 256) p += g_bsum[i];
    #pragma unroll
    for (int o = 16; o > 0; o >>= 1)
        p += __shfl_down_sync(0xFFFFFFFF, p, o);
    if ((t & 31) == 0) wsum[t >> 5] = p;
    __syncthreads();
    if (t == 0) {
        int s = 0;
        #pragma unroll
        for (int w = 0; w < 8; w++) s += wsum[w];
        s_base = s;
    }

    int i = b * 256 + t;
    int d = (i < N_NODES) ? g_deg[i] : 0;
    part[t] = d;
    __syncthreads();
    for (int off = 1; off < 256; off <<= 1) {
        int v = (t >= off) ? part[t - off] : 0;
        __syncthreads();
        part[t] += v;
        __syncthreads();
    }
    int base = s_base;
    if (i < N_NODES) {
        int off = base + part[t] - d;   // exclusive
        g_off[i] = off;
        g_cur[i] = off;
    }
    if (b == NSCAN_BLOCKS - 1 && t == 255)
        g_off[N_NODES] = base + part[255];
}

__global__ void fill_csr_kernel(const int* __restrict__ src,
                                const int* __restrict__ dst) {
    int e = blockIdx.x * blockDim.x + threadIdx.x;
    if (e < N_EDGES) {
        int p = atomicAdd(&g_cur[dst[e]], 1);
        g_csr[p] = src[e];
    }
}

// ===========================================================================
// Gather-sum kernels
// ===========================================================================
__global__ __launch_bounds__(256)
void gather_sum_128(const float* __restrict__ feat, __half* __restrict__ o) {
    int n = blockIdx.x * 8 + (threadIdx.x >> 5);
    int t = threadIdx.x & 31;
    int lo = g_off[n], hi = g_off[n + 1];
    float4 acc = make_float4(0.f, 0.f, 0.f, 0.f);
    int j = lo;
    if (j < hi) {
        float4 cur = reinterpret_cast<const float4*>(
            feat + (size_t)g_csr[j] * IN_DIM)[t];
        for (++j; j < hi; ++j) {
            float4 nxt = reinterpret_cast<const float4*>(
                feat + (size_t)g_csr[j] * IN_DIM)[t];
            acc.x += cur.x; acc.y += cur.y; acc.z += cur.z; acc.w += cur.w;
            cur = nxt;
        }
        acc.x += cur.x; acc.y += cur.y; acc.z += cur.z; acc.w += cur.w;
    }
    __half2 h0 = __floats2half2_rn(acc.x, acc.y);
    __half2 h1v = __floats2half2_rn(acc.z, acc.w);
    __half2* op = reinterpret_cast<__half2*>(o + (size_t)n * IN_DIM) + t * 2;
    op[0] = h0;
    op[1] = h1v;
}

__global__ __launch_bounds__(256)
void gather_sum_512h(const __half* __restrict__ h, __half* __restrict__ o) {
    int n = blockIdx.x * 4 + (threadIdx.x >> 6);
    int t = threadIdx.x & 63;
    int lo = g_off[n], hi = g_off[n + 1];
    float acc[8];
    #pragma unroll
    for (int i = 0; i < 8; i++) acc[i] = 0.f;
    int j = lo;
    if (j < hi) {
        uint4 cur = reinterpret_cast<const uint4*>(
            h + (size_t)g_csr[j] * HID)[t];
        for (++j; j < hi; ++j) {
            uint4 nxt = reinterpret_cast<const uint4*>(
                h + (size_t)g_csr[j] * HID)[t];
            const __half2* hp = reinterpret_cast<const __half2*>(&cur);
            #pragma unroll
            for (int i = 0; i < 4; i++) {
                float2 v = __half22float2(hp[i]);
                acc[i * 2 + 0] += v.x;
                acc[i * 2 + 1] += v.y;
            }
            cur = nxt;
        }
        const __half2* hp = reinterpret_cast<const __half2*>(&cur);
        #pragma unroll
        for (int i = 0; i < 4; i++) {
            float2 v = __half22float2(hp[i]);
            acc[i * 2 + 0] += v.x;
            acc[i * 2 + 1] += v.y;
        }
    }
    uint4 out;
    __half2* op = reinterpret_cast<__half2*>(&out);
    #pragma unroll
    for (int i = 0; i < 4; i++)
        op[i] = __floats2half2_rn(acc[i * 2], acc[i * 2 + 1]);
    reinterpret_cast<uint4*>(o + (size_t)n * HID)[t] = out;
}

// ===========================================================================
// fp16 tensor-core GEMM, templated N-tile (NT in {256,128}):
//   C[M,Nreal] = relu(A@W + bias)
// CTA 128m x NTn, BK=64, 8 warps (32m x NT/2 n), 2-stage cp.async.
// 144B smem rows -> conflict-free ldmatrix; smem-staged coalesced epilogue.
// NT=256 instantiation is identical to the proven R7 kernel.
// ===========================================================================
#define GROW  144u
#define ATILE 18432u

template <bool HALF_OUT, int NT>
__global__ __launch_bounds__(256, 1)
void gemm_fp16(const __half* __restrict__ A, const __half* __restrict__ B,
               const float* __restrict__ bias, void* __restrict__ Cout,
               int M, int Nreal, int K)
{
    constexpr uint32_t BTILE = (uint32_t)NT * GROW;   // B tile bytes
    constexpr uint32_t GBUF  = ATILE + BTILE;
    constexpr int      NG    = NT / 32;               // ldsm B groups per warp
    constexpr uint32_t STG   = (uint32_t)NT * 2 + 16; // staging row stride
    constexpr int      UPR   = NT / 8;                // uint4 units per row

    extern __shared__ char dsm[];
    const uint32_t sbase = smem_to_u32(dsm);
    const int tid  = threadIdx.x;
    const int lane = tid & 31;
    const int wid  = tid >> 5;
    const int row0 = blockIdx.y * 128;
    const int col0 = blockIdx.x * NT;
    const int NC   = K / 64;

    const int m_base = (wid & 3) * 32;
    const int n_base = (wid >> 2) * (NT / 2);

    float acc[2][NT / 16][4];
    #pragma unroll
    for (int i = 0; i < 2; i++)
        #pragma unroll
        for (int j = 0; j < NT / 16; j++)
            #pragma unroll
            for (int q = 0; q < 4; q++) acc[i][j][q] = 0.f;

    auto load_chunk = [&](int buf, int c) {
        uint32_t s = sbase + (uint32_t)buf * GBUF;
        #pragma unroll
        for (int i = 0; i < 4; i++) {
            int f  = tid + i * 256;
            int m  = f >> 3, k8 = f & 7;
            int gm = row0 + m;
            uint32_t ok = (gm < M) ? 16u : 0u;
            int gmc = (gm < M) ? gm : 0;
            cpa16(s + m * GROW + k8 * 16,
                  A + (size_t)gmc * K + c * 64 + k8 * 8, ok);
        }
        #pragma unroll
        for (int i = 0; i < NT / 32; i++) {
            int f = tid + i * 256;
            int n = f >> 3, k8 = f & 7;
            cpa16(s + ATILE + n * GROW + k8 * 16,
                  B + (size_t)(col0 + n) * K + c * 64 + k8 * 8, 16u);
        }
        CP_COMMIT();
    };

    load_chunk(0, 0);

    for (int c = 0; c < NC; c++) {
        const int buf = c & 1;
        if (c + 1 < NC) {
            load_chunk(buf ^ 1, c + 1);
            CP_WAIT(1);
        } else {
            CP_WAIT(0);
        }
        __syncthreads();

        const uint32_t sA = sbase + (uint32_t)buf * GBUF;
        const uint32_t sB = sA + ATILE;

        #pragma unroll
        for (int ks = 0; ks < 4; ks++) {
            uint32_t a[2][4];
            #pragma unroll
            for (int im = 0; im < 2; im++) {
                uint32_t ra = sA
                    + (uint32_t)(m_base + im * 16 + (lane & 15)) * GROW
                    + (uint32_t)(ks * 16 + ((lane >> 4) * 8)) * 2;
                ldsm_x4(a[im][0], a[im][1], a[im][2], a[im][3], ra);
            }
            #pragma unroll
            for (int g = 0; g < NG; g++) {
                uint32_t bh[4];
                uint32_t rb = sB
                    + (uint32_t)(n_base + g * 16 +
                                 ((lane >> 4) & 1) * 8 + (lane & 7)) * GROW
                    + (uint32_t)(ks * 16 + ((lane >> 3) & 1) * 8) * 2;
                ldsm_x4(bh[0], bh[1], bh[2], bh[3], rb);
                #pragma unroll
                for (int im = 0; im < 2; im++) {
                    #pragma unroll
                    for (int sub = 0; sub < 2; sub++) {
                        mma_fp16(acc[im][g * 2 + sub], a[im],
                                 bh[sub * 2], bh[sub * 2 + 1]);
                    }
                }
            }
        }
        __syncthreads();
    }

    const bool full_n = (col0 + NT <= Nreal);
    if (HALF_OUT && full_n) {
        #pragma unroll
        for (int im = 0; im < 2; im++) {
            int ml = m_base + im * 16 + (lane >> 2);
            #pragma unroll
            for (int j = 0; j < NT / 16; j++) {
                int nl = n_base + j * 8 + (lane & 3) * 2;
                float b0 = bias[col0 + nl], b1 = bias[col0 + nl + 1];
                __half2* p0 = reinterpret_cast<__half2*>(
                    dsm + (uint32_t)ml * STG + nl * 2);
                *p0 = __floats2half2_rn(fmaxf(acc[im][j][0] + b0, 0.f),
                                        fmaxf(acc[im][j][1] + b1, 0.f));
                __half2* p1 = reinterpret_cast<__half2*>(
                    dsm + (uint32_t)(ml + 8) * STG + nl * 2);
                *p1 = __floats2half2_rn(fmaxf(acc[im][j][2] + b0, 0.f),
                                        fmaxf(acc[im][j][3] + b1, 0.f));
            }
        }
        __syncthreads();
        __half* C = (__half*)Cout;
        #pragma unroll
        for (int p = 0; p < UPR * 128 / 256; p++) {
            int idx = tid + p * 256;
            int r = idx / UPR, u = idx % UPR;
            int gm = row0 + r;
            if (gm < M) {
                uint4 v = *reinterpret_cast<const uint4*>(
                    dsm + (uint32_t)r * STG + u * 16);
                *reinterpret_cast<uint4*>(
                    C + (size_t)gm * Nreal + col0 + u * 8) = v;
            }
        }
    } else {
        #pragma unroll
        for (int im = 0; im < 2; im++) {
            int m0 = row0 + m_base + im * 16 + (lane >> 2);
            #pragma unroll
            for (int j = 0; j < NT / 16; j++) {
                int n = col0 + n_base + j * 8 + (lane & 3) * 2;
                #pragma unroll
                for (int q = 0; q < 4; q++) {
                    int mm = m0 + (q >> 1) * 8;
                    int nn = n + (q & 1);
                    if (mm < M && nn < Nreal) {
                        float v = fmaxf(acc[im][j][q] + bias[nn], 0.f);
                        if (HALF_OUT)
                            ((__half*)Cout)[(size_t)mm * Nreal + nn] =
                                __float2half_rn(v);
                        else
                            ((float*)Cout)[(size_t)mm * Nreal + nn] = v;
                    }
                }
            }
        }
    }
}

#define GDSM256 (2u * (ATILE + 256u * GROW))   // 110592
#define GDSM128 (2u * (ATILE + 128u * GROW))   //  73728

// ===========================================================================
// Fused MLP2 + classifier: m2 = relu(m1@lw2 + lb2); out = m2@cw + cb
// ===========================================================================
#define BM 128
#define BN 128
#define BK8 8
#define TM 8
#define TN 8
#define MLP2_SMEM (BM * MLP2 * 4)   // 51200 B

__global__ __launch_bounds__(256)
void mlp2_cls_kernel(const float* __restrict__ A, const float* __restrict__ B,
                     const float* __restrict__ bias,
                     const float* __restrict__ cw, const float* __restrict__ cb,
                     float* __restrict__ out, int M, int N, int K) {
    extern __shared__ float sbuf[];
    float* As = sbuf;                 // [BK8][BM]
    float* Bs = sbuf + BK8 * BM;      // [BK8][BN]
    const int tid  = threadIdx.x;
    const int row0 = blockIdx.y * BM;
    const int tx = tid & 15;
    const int ty = tid >> 4;
    float acc[TM][TN];
    #pragma unroll
    for (int i = 0; i < TM; i++)
        #pragma unroll
        for (int j = 0; j < TN; j++) acc[i][j] = 0.f;

    for (int k0 = 0; k0 < K; k0 += BK8) {
        #pragma unroll
        for (int i = 0; i < 4; i++) {
            int idx = tid + i * 256;
            int m = idx >> 3, k = idx & 7;
            int gm = row0 + m, gk = k0 + k;
            As[k * BM + m] = (gm < M && gk < K) ? A[(size_t)gm * K + gk] : 0.f;
        }
        #pragma unroll
        for (int i = 0; i < 4; i++) {
            int idx = tid + i * 256;
            int k = idx >> 7, n = idx & 127;
            int gk = k0 + k;
            Bs[k * BN + n] = (gk < K && n < N) ? B[(size_t)gk * N + n] : 0.f;
        }
        __syncthreads();
        #pragma unroll
        for (int k = 0; k < BK8; k++) {
            float a[TM], b[TN];
            #pragma unroll
            for (int i = 0; i < TM; i++) a[i] = As[k * BM + ty * TM + i];
            #pragma unroll
            for (int j = 0; j < TN; j++) b[j] = Bs[k * BN + tx * TN + j];
            #pragma unroll
            for (int i = 0; i < TM; i++)
                #pragma unroll
                for (int j = 0; j < TN; j++)
                    acc[i][j] += a[i] * b[j];
        }
        __syncthreads();
    }

    float* sm2 = sbuf;   // [BM][MLP2]
    __syncthreads();
    #pragma unroll
    for (int i = 0; i < TM; i++) {
        int lm = ty * TM + i;
        #pragma unroll
        for (int j = 0; j < TN; j++) {
            int n = tx * TN + j;
            if (n < N)
                sm2[lm * MLP2 + n] = fmaxf(acc[i][j] + bias[n], 0.f);
        }
    }
    __syncthreads();
    if (tid < BM) {
        int gm = row0 + tid;
        if (gm < M) {
            float a0 = cb[0], a1 = cb[1];
            const float* row = sm2 + tid * MLP2;
            #pragma unroll 4
            for (int k = 0; k < MLP2; k++) {
                float v = row[k];
                a0 += v * cw[k * 2 + 0];
                a1 += v * cw[k * 2 + 1];
            }
            out[gm * 2 + 0] = a0;
            out[gm * 2 + 1] = a1;
        }
    }
}

// ===========================================================================
// Mean pool (sorted node2graph, fp16 input) + concat descriptors -> X fp16
// ===========================================================================
__device__ __forceinline__ int lower_bound_dev(const int* a, int n, int v) {
    int lo = 0, hi = n;
    while (lo < hi) {
        int m = (lo + hi) >> 1;
        if (a[m] < v) lo = m + 1; else hi = m;
    }
    return lo;
}
__global__ void pool_concat_kernel(const __half* __restrict__ h2,
                                   const float* __restrict__ desc,
                                   const int* __restrict__ n2g,
                                   __half* __restrict__ X) {
    int g = blockIdx.x;
    __shared__ int s_lo, s_hi;
    if (threadIdx.x == 0) s_lo = lower_bound_dev(n2g, N_NODES, g);
    if (threadIdx.x == 1) s_hi = lower_bound_dev(n2g, N_NODES, g + 1);
    __syncthreads();
    int lo = s_lo, hi = s_hi;
    float inv = 1.f / fmaxf((float)(hi - lo), 1.f);
    int t = threadIdx.x;
    float2 a0 = make_float2(0.f, 0.f), a1 = make_float2(0.f, 0.f);
    for (int i = lo; i < hi; i++) {
        const __half2* row = reinterpret_cast<const __half2*>(
            h2 + (size_t)i * HID);
        float2 v0 = __half22float2(row[t * 2 + 0]);
        float2 v1 = __half22float2(row[t * 2 + 1]);
        a0.x += v0.x; a0.y += v0.y;
        a1.x += v1.x; a1.y += v1.y;
    }
    size_t rb = (size_t)g * XPAD;
    __half2* xrow = reinterpret_cast<__half2*>(X + rb);
    xrow[t * 2 + 0] = __floats2half2_rn(a0.x * inv, a0.y * inv);
    xrow[t * 2 + 1] = __floats2half2_rn(a1.x * inv, a1.y * inv);
    for (int d = t; d < N_DESC; d += 128)
        X[rb + HID + d] = __float2half_rn(desc[(size_t)g * N_DESC + d]);
    for (int d = t; d < XPAD - XDIM; d += 128)
        X[rb + XDIM + d] = __float2half_rn(0.f);
}

// ===========================================================================
// Launch
// ===========================================================================
extern "C" void kernel_launch(void* const* d_in, const int* in_sizes, int n_in,
                              void* d_out, int out_size) {
    const float* features    = (const float*)d_in[0];
    const float* descriptors = (const float*)d_in[1];
    const int*   src         = (const int*)  d_in[2];
    const int*   dst         = (const int*)  d_in[3];
    const int*   n2g         = (const int*)  d_in[4];
    const float* W1          = (const float*)d_in[5];
    const float* b1          = (const float*)d_in[6];
    const float* W2          = (const float*)d_in[7];
    const float* b2          = (const float*)d_in[8];
    const float* lw1         = (const float*)d_in[9];
    const float* lb1         = (const float*)d_in[10];
    const float* lw2         = (const float*)d_in[11];
    const float* lb2         = (const float*)d_in[12];
    const float* cw          = (const float*)d_in[13];
    const float* cb          = (const float*)d_in[14];
    float* out = (float*)d_out;

    __half *a0, *h1, *a1, *h2, *X, *B1, *B2, *BL;
    float *m1;
    cudaGetSymbolAddress((void**)&a0, g_a0);
    cudaGetSymbolAddress((void**)&h1, g_h1);
    cudaGetSymbolAddress((void**)&a1, g_a1);
    cudaGetSymbolAddress((void**)&h2, g_h2);
    cudaGetSymbolAddress((void**)&X,  g_X);
    cudaGetSymbolAddress((void**)&m1, g_m1);
    cudaGetSymbolAddress((void**)&B1, g_B1);
    cudaGetSymbolAddress((void**)&B2, g_B2);
    cudaGetSymbolAddress((void**)&BL, g_BL);

    cudaFuncSetAttribute((const void*)gemm_fp16<true, 256>,
                         cudaFuncAttributeMaxDynamicSharedMemorySize, GDSM256);
    cudaFuncSetAttribute((const void*)gemm_fp16<false, 128>,
                         cudaFuncAttributeMaxDynamicSharedMemorySize, GDSM128);
    cudaFuncSetAttribute((const void*)mlp2_cls_kernel,
                         cudaFuncAttributeMaxDynamicSharedMemorySize, MLP2_SMEM);

    // init (zero deg + weight prep)
    init_kernel<<<(INIT_TOTAL + 255) / 256, 256>>>(W1, W2, lw1, B1, B2, BL);
    // CSR build
    count_deg_kernel<<<(N_EDGES + 255) / 256, 256>>>(dst);
    scan_partial_kernel<<<NSCAN_BLOCKS, 256>>>();
    scan_apply_kernel<<<NSCAN_BLOCKS, 256>>>();
    fill_csr_kernel<<<(N_EDGES + 255) / 256, 256>>>(src, dst);

    // Layer 1
    gather_sum_128<<<N_NODES / 8, 256>>>(features, a0);
    { dim3 g(2, (N_NODES + 127) / 128);
      gemm_fp16<true, 256><<<g, 256, GDSM256>>>(a0, B1, b1, h1,
                                                N_NODES, HID, IN_DIM); }

    // Layer 2
    gather_sum_512h<<<N_NODES / 4, 256>>>(h1, a1);
    { dim3 g(2, (N_NODES + 127) / 128);
      gemm_fp16<true, 256><<<g, 256, GDSM256>>>(a1, B2, b2, h2,
                                                N_NODES, HID, HID); }

    // Pool + concat
    pool_concat_kernel<<<N_GRAPHS, 128>>>(h2, descriptors, n2g, X);

    // MLP head: NT=128 -> grid(4, 32) = 128 CTAs (was 64)
    { dim3 g(4, (N_GRAPHS + 127) / 128);
      gemm_fp16<false, 128><<<g, 256, GDSM128>>>(X, BL, lb1, m1,
                                                 N_GRAPHS, MLP1, XPAD); }
    { dim3 g(1, (N_GRAPHS + 127) / 128);
      mlp2_cls_kernel<<<g, 256, MLP2_SMEM>>>(m1, lw2, lb2, cw, cb, out,
                                             N_GRAPHS, MLP2, MLP1); }
}